// round 1
// baseline (speedup 1.0000x reference)
#include <cuda_runtime.h>

// HeavyCompressor: fused dual-GEMM + windowed softmax-compress.
//   c = h @ w_kv^T, z = h @ w_z^T  (h:[B*S, D], w:[HD, D])
//   per aligned window of M=8 rows: weights = softmax(z + b, axis=window)
//   out[window, hd] = sum_r weights[r,hd] * c[r,hd]   -> written twice (tuple)
//
// Round-1 baseline: fp32 SIMT, fully fused. Each thread owns one complete
// 8-row window x 4 hd columns, so softmax is thread-local (no shuffles).

constexpr int D_  = 2048;
constexpr int HD_ = 128;
constexpr int M_  = 8;
constexpr int BQ  = 64;            // rows per CTA (8 windows)
constexpr int KT  = 16;            // K tile
constexpr int NT  = D_ / KT;       // 128 K tiles

__global__ __launch_bounds__(256, 2)
void heavy_compressor_fused(const float* __restrict__ hmat,
                            const float* __restrict__ wkv,
                            const float* __restrict__ wz,
                            const float* __restrict__ bias,
                            float* __restrict__ out,
                            int write_second, int out_half)
{
    // k-major (transposed) tiles: conflict-free float4 reads in the mainloop
    __shared__ float hs [2][KT][BQ];    //  8 KB
    __shared__ float wks[2][KT][HD_];   // 16 KB
    __shared__ float wzs[2][KT][HD_];   // 16 KB

    const int tid = threadIdx.x;
    const int tc  = tid & 31;          // hd column group: cols 4*tc..4*tc+3
    const int tr  = tid >> 5;          // window index within CTA: rows 8*tr..8*tr+7
    const long long row0 = (long long)blockIdx.x * BQ;

    float ca[M_][4], za[M_][4];
#pragma unroll
    for (int r = 0; r < M_; ++r)
#pragma unroll
        for (int j = 0; j < 4; ++j) { ca[r][j] = 0.f; za[r][j] = 0.f; }

    // loader mapping (float4 granularity)
    const int h_row = tid >> 2;        // 0..63
    const int h_kg  = tid & 3;         // 0..3  (k-group of 4)

    const float* hbase = hmat + row0 * D_;

    float4 sh;
    float4 swk[2], swz[2];

    // ---- preload tile 0 ----
    sh = *(const float4*)(hbase + (long long)h_row * D_ + h_kg * 4);
#pragma unroll
    for (int i = 0; i < 2; ++i) {
        int idx = tid + 256 * i;
        int col = idx >> 2, kg = idx & 3;
        swk[i] = *(const float4*)(wkv + col * D_ + kg * 4);
        swz[i] = *(const float4*)(wz  + col * D_ + kg * 4);
    }
    {
        float vv[4] = {sh.x, sh.y, sh.z, sh.w};
#pragma unroll
        for (int j = 0; j < 4; ++j) hs[0][h_kg * 4 + j][h_row] = vv[j];
#pragma unroll
        for (int i = 0; i < 2; ++i) {
            int idx = tid + 256 * i;
            int col = idx >> 2, kg = idx & 3;
            float a[4]  = {swk[i].x, swk[i].y, swk[i].z, swk[i].w};
            float b2[4] = {swz[i].x, swz[i].y, swz[i].z, swz[i].w};
#pragma unroll
            for (int j = 0; j < 4; ++j) {
                wks[0][kg * 4 + j][col] = a[j];
                wzs[0][kg * 4 + j][col] = b2[j];
            }
        }
    }
    __syncthreads();

    // ---- mainloop, double buffered ----
    for (int t = 0; t < NT; ++t) {
        const int cur = t & 1;
        const int k0  = (t + 1) * KT;

        if (t + 1 < NT) {   // stage next tile into registers
            sh = *(const float4*)(hbase + (long long)h_row * D_ + k0 + h_kg * 4);
#pragma unroll
            for (int i = 0; i < 2; ++i) {
                int idx = tid + 256 * i;
                int col = idx >> 2, kg = idx & 3;
                swk[i] = *(const float4*)(wkv + col * D_ + k0 + kg * 4);
                swz[i] = *(const float4*)(wz  + col * D_ + k0 + kg * 4);
            }
        }

        const float4* h4 = (const float4*)hs[cur];   // [KT][BQ/4]
        const float4* k4 = (const float4*)wks[cur];  // [KT][HD/4]
        const float4* z4 = (const float4*)wzs[cur];
#pragma unroll
        for (int k = 0; k < KT; ++k) {
            float4 h0 = h4[k * (BQ / 4) + 2 * tr];       // broadcast within warp
            float4 h1 = h4[k * (BQ / 4) + 2 * tr + 1];
            float4 a  = k4[k * (HD_ / 4) + tc];          // conflict-free
            float4 bb = z4[k * (HD_ / 4) + tc];
            float hr[8] = {h0.x, h0.y, h0.z, h0.w, h1.x, h1.y, h1.z, h1.w};
#pragma unroll
            for (int r = 0; r < 8; ++r) {
                ca[r][0] = fmaf(hr[r], a.x,  ca[r][0]);
                ca[r][1] = fmaf(hr[r], a.y,  ca[r][1]);
                ca[r][2] = fmaf(hr[r], a.z,  ca[r][2]);
                ca[r][3] = fmaf(hr[r], a.w,  ca[r][3]);
                za[r][0] = fmaf(hr[r], bb.x, za[r][0]);
                za[r][1] = fmaf(hr[r], bb.y, za[r][1]);
                za[r][2] = fmaf(hr[r], bb.z, za[r][2]);
                za[r][3] = fmaf(hr[r], bb.w, za[r][3]);
            }
        }

        if (t + 1 < NT) {   // commit staged tile into the other buffer
            int nb = cur ^ 1;
            float vv[4] = {sh.x, sh.y, sh.z, sh.w};
#pragma unroll
            for (int j = 0; j < 4; ++j) hs[nb][h_kg * 4 + j][h_row] = vv[j];
#pragma unroll
            for (int i = 0; i < 2; ++i) {
                int idx = tid + 256 * i;
                int col = idx >> 2, kg = idx & 3;
                float a[4]  = {swk[i].x, swk[i].y, swk[i].z, swk[i].w};
                float b2[4] = {swz[i].x, swz[i].y, swz[i].z, swz[i].w};
#pragma unroll
                for (int j = 0; j < 4; ++j) {
                    wks[nb][kg * 4 + j][col] = a[j];
                    wzs[nb][kg * 4 + j][col] = b2[j];
                }
            }
        }
        __syncthreads();
    }

    // ---- epilogue: bias + window softmax + weighted sum (all thread-local) ----
    const int col0 = tc * 4;
    float res[4];
#pragma unroll
    for (int j = 0; j < 4; ++j) {
        float zb[8];
        float mx = -1e30f;
#pragma unroll
        for (int r = 0; r < 8; ++r) {
            zb[r] = za[r][j] + bias[r * HD_ + col0 + j];
            mx = fmaxf(mx, zb[r]);
        }
        float s = 0.f, acc = 0.f;
#pragma unroll
        for (int r = 0; r < 8; ++r) {
            float e = __expf(zb[r] - mx);
            s += e;
            acc = fmaf(e, ca[r][j], acc);
        }
        res[j] = acc / s;
    }

    const long long widx = row0 / M_ + tr;   // global window index
    float4 v = make_float4(res[0], res[1], res[2], res[3]);
    *(float4*)(out + widx * HD_ + col0) = v;
    if (write_second)
        *(float4*)(out + out_half + widx * HD_ + col0) = v;
}

extern "C" void kernel_launch(void* const* d_in, const int* in_sizes, int n_in,
                              void* d_out, int out_size)
{
    const float* h    = (const float*)d_in[0];
    const float* wkv  = (const float*)d_in[1];
    const float* wz   = (const float*)d_in[2];
    const float* bias = (const float*)d_in[3];

    const int rows = in_sizes[0] / D_;            // B*S = 32768
    const int base = (rows / M_) * HD_;           // windows * HD = 524288
    const int write_second = (out_size >= 2 * base) ? 1 : 0;

    heavy_compressor_fused<<<rows / BQ, 256>>>(
        h, wkv, wz, bias, (float*)d_out, write_second, base);
}

// round 3
// speedup vs baseline: 2.6866x; 2.6866x over previous
#include <cuda_runtime.h>
#include <cstdint>

// ---------------------------------------------------------------------------
// HeavyCompressor round 3: mma.sync (m16n8k8 tf32) dual-GEMM + fused softmax.
// compute_100 target => no tcgen05; legacy tensor path via HMMA.
//   CTA: 128 rows x 256 cols (cols 0-127 = c = h@wkv^T, 128-255 = z = h@wz^T)
//   16 warps, warp tile 64x32, fp32 accum in registers.
//   4-stage cp.async ring, K-tile 16. Epilogue through smem (union with ring).
// ---------------------------------------------------------------------------

constexpr int D_    = 2048;
constexpr int HD_   = 128;
constexpr int CTA_M = 128;
constexpr int KT    = 16;
constexpr int NK    = D_ / KT;          // 128
constexpr int NSTAGE = 4;
constexpr int SA    = KT + 4;           // padded stride (20 floats) — conflict-free frags
constexpr int A_FLOATS = CTA_M * SA;    // 2560
constexpr int B_FLOATS = 256 * SA;      // 5120
constexpr int STAGE_FLOATS = A_FLOATS + B_FLOATS;          // 7680 (30 KB)
constexpr int EPI_STR = 276;            // padded epilogue row stride
constexpr int EPI_FLOATS = CTA_M * EPI_STR;                // 35328 (138 KB)
constexpr int RING_FLOATS = STAGE_FLOATS * NSTAGE;         // 30720 (120 KB)
constexpr int SMEM_FLOATS = (RING_FLOATS > EPI_FLOATS) ? RING_FLOATS : EPI_FLOATS;
constexpr int SMEM_BYTES = SMEM_FLOATS * 4;                // 141312

__device__ __forceinline__ uint32_t smem_u32(const void* p) {
    uint32_t a;
    asm("{ .reg .u64 t; cvta.to.shared.u64 t, %1; cvt.u32.u64 %0, t; }" : "=r"(a) : "l"(p));
    return a;
}
__device__ __forceinline__ void cp16(const void* dst, const void* src) {
    asm volatile("cp.async.cg.shared.global [%0], [%1], 16;"
                 :: "r"(smem_u32(dst)), "l"(src) : "memory");
}
__device__ __forceinline__ uint32_t f2tf(float f) {
    uint32_t r;
    asm("cvt.rna.tf32.f32 %0, %1;" : "=r"(r) : "f"(f));
    return r;
}
__device__ __forceinline__ void mma_tf32(float* c, const uint32_t* a, const uint32_t* b) {
    asm volatile(
        "mma.sync.aligned.m16n8k8.row.col.f32.tf32.tf32.f32 "
        "{%0,%1,%2,%3}, {%4,%5,%6,%7}, {%8,%9}, {%0,%1,%2,%3};"
        : "+f"(c[0]), "+f"(c[1]), "+f"(c[2]), "+f"(c[3])
        : "r"(a[0]), "r"(a[1]), "r"(a[2]), "r"(a[3]), "r"(b[0]), "r"(b[1]));
}

__global__ __launch_bounds__(512, 1)
void heavy_compressor_mma(const float* __restrict__ h,
                          const float* __restrict__ wkv,
                          const float* __restrict__ wz,
                          const float* __restrict__ bias,
                          float* __restrict__ out,
                          int write_second, int out_half)
{
    extern __shared__ float smem[];

    const int tid  = threadIdx.x;
    const int wid  = tid >> 5;
    const int lane = tid & 31;
    const int g    = lane >> 2;          // group id (row within frag)
    const int tg   = lane & 3;           // thread-in-group (col within frag)
    const int warp_m = wid & 1;          // 2 m-blocks of 64 rows
    const int warp_n = wid >> 1;         // 8 n-blocks of 32 cols
    const long long row0 = (long long)blockIdx.x * CTA_M;

    float acc[4][4][4];                  // [mi][ni][frag]
#pragma unroll
    for (int mi = 0; mi < 4; ++mi)
#pragma unroll
        for (int ni = 0; ni < 4; ++ni)
#pragma unroll
            for (int j = 0; j < 4; ++j) acc[mi][ni][j] = 0.f;

    // ---- stage loader: 512 A-granules + 1024 B-granules of 16B ----
    auto load_stage = [&](int s) {
        float* as = smem + (s % NSTAGE) * STAGE_FLOATS;
        float* bs = as + A_FLOATS;
        const int k0 = s * KT;
        {
            int r = tid >> 2, gk = tid & 3;                    // A: 128 rows x 4 granules
            cp16(as + r * SA + gk * 4, h + (row0 + r) * D_ + k0 + gk * 4);
        }
#pragma unroll
        for (int i = 0; i < 2; ++i) {                          // B: 256 rows x 4 granules
            int idx = tid + 512 * i;
            int r = idx >> 2, gk = idx & 3;
            const float* src = (r < 128) ? (wkv + (long long)r * D_)
                                         : (wz + (long long)(r - 128) * D_);
            cp16(bs + r * SA + gk * 4, src + k0 + gk * 4);
        }
        asm volatile("cp.async.commit_group;" ::: "memory");
    };

    load_stage(0);
    load_stage(1);
    load_stage(2);

    // ---- mainloop ----
#pragma unroll 1
    for (int t = 0; t < NK; ++t) {
        asm volatile("cp.async.wait_group 2;" ::: "memory");
        __syncthreads();

        if (t + 3 < NK) load_stage(t + 3);
        else asm volatile("cp.async.commit_group;" ::: "memory");  // keep FIFO aligned

        const float* as = smem + (t % NSTAGE) * STAGE_FLOATS;
        const float* bs = as + A_FLOATS;

#pragma unroll
        for (int ks = 0; ks < 2; ++ks) {
            const int kc = ks * 8 + tg;
            uint32_t a[4][4], b[4][2];
#pragma unroll
            for (int mi = 0; mi < 4; ++mi) {
                const float* ap = as + (warp_m * 64 + mi * 16 + g) * SA + kc;
                a[mi][0] = f2tf(ap[0]);
                a[mi][1] = f2tf(ap[8 * SA]);
                a[mi][2] = f2tf(ap[4]);
                a[mi][3] = f2tf(ap[8 * SA + 4]);
            }
#pragma unroll
            for (int ni = 0; ni < 4; ++ni) {
                const float* bp = bs + (warp_n * 32 + ni * 8 + g) * SA + kc;
                b[ni][0] = f2tf(bp[0]);
                b[ni][1] = f2tf(bp[4]);
            }
#pragma unroll
            for (int mi = 0; mi < 4; ++mi)
#pragma unroll
                for (int ni = 0; ni < 4; ++ni)
                    mma_tf32(acc[mi][ni], a[mi], b[ni]);
        }
        __syncthreads();
    }

    // ---- epilogue: accums -> smem, then windowed softmax-compress ----
    float* epi = smem;     // union with the (now dead) cp.async ring
    __syncthreads();
#pragma unroll
    for (int mi = 0; mi < 4; ++mi)
#pragma unroll
        for (int ni = 0; ni < 4; ++ni) {
            int m0 = warp_m * 64 + mi * 16 + g;
            int n0 = warp_n * 32 + ni * 8 + 2 * tg;
            *(float2*)(epi + m0 * EPI_STR + n0)       = make_float2(acc[mi][ni][0], acc[mi][ni][1]);
            *(float2*)(epi + (m0 + 8) * EPI_STR + n0) = make_float2(acc[mi][ni][2], acc[mi][ni][3]);
        }
    __syncthreads();

    const int win = tid >> 5;            // 16 windows of 8 rows
    float zb[8][4], cc[8][4];
#pragma unroll
    for (int r = 0; r < 8; ++r) {
        const float* rp = epi + (win * 8 + r) * EPI_STR;
        float4 c4 = *(const float4*)(rp + lane * 4);
        float4 z4 = *(const float4*)(rp + HD_ + lane * 4);
        float4 b4 = *(const float4*)(bias + r * HD_ + lane * 4);
        cc[r][0] = c4.x; cc[r][1] = c4.y; cc[r][2] = c4.z; cc[r][3] = c4.w;
        zb[r][0] = z4.x + b4.x; zb[r][1] = z4.y + b4.y;
        zb[r][2] = z4.z + b4.z; zb[r][3] = z4.w + b4.w;
    }
    float res[4];
#pragma unroll
    for (int i = 0; i < 4; ++i) {
        float mx = zb[0][i];
#pragma unroll
        for (int r = 1; r < 8; ++r) mx = fmaxf(mx, zb[r][i]);
        float s = 0.f, a = 0.f;
#pragma unroll
        for (int r = 0; r < 8; ++r) {
            float e = __expf(zb[r][i] - mx);
            s += e;
            a = fmaf(e, cc[r][i], a);
        }
        res[i] = a / s;
    }
    const long long w = (long long)blockIdx.x * 16 + win;
    float4 v = make_float4(res[0], res[1], res[2], res[3]);
    float* dst = out + w * HD_ + lane * 4;
    *(float4*)dst = v;
    if (write_second) *(float4*)(dst + out_half) = v;
}

extern "C" void kernel_launch(void* const* d_in, const int* in_sizes, int n_in,
                              void* d_out, int out_size)
{
    const float* h    = (const float*)d_in[0];
    const float* wkv  = (const float*)d_in[1];
    const float* wz   = (const float*)d_in[2];
    const float* bias = (const float*)d_in[3];

    const int rows = in_sizes[0] / D_;              // 32768
    const int base = (rows / 8) * HD_;              // 524288
    const int write_second = (out_size >= 2 * base) ? 1 : 0;

    cudaFuncSetAttribute(heavy_compressor_mma,
                         cudaFuncAttributeMaxDynamicSharedMemorySize, SMEM_BYTES);
    heavy_compressor_mma<<<rows / CTA_M, 512, SMEM_BYTES>>>(
        h, wkv, wz, bias, (float*)d_out, write_second, base);
}